// round 5
// baseline (speedup 1.0000x reference)
#include <cuda_runtime.h>

// LIF neuron recurrence, fully parallel across B*N neurons, serial over T.
//   out[t]  = (mem > 1.0f) ? 1 : 0
//   mem     = (0.5f*mem + syn) * (1 - out[t])
//   syn     = in[t]
// inputs: [T=100, B=256, N=2048] fp32 contiguous; output same shape.
//
// R5: float2/thread -> 262144 threads (8192 warps, ~54/SM, occ ~84%), double
// R1's warp count. Empirical trend R1..R4: more resident warps -> higher
// DRAM%, mechanism = more independent outstanding-load streams overlapping
// DRAM banks. Issue was 12.8% at float4 so 2x inst count is safe.

constexpr int T_STEPS = 100;

__global__ void __launch_bounds__(256) lif_kernel(
    const float2* __restrict__ in,
    float2* __restrict__ out,
    int n2)
{
    int i = blockIdx.x * blockDim.x + threadIdx.x;
    if (i >= n2) return;

    float2 mem = make_float2(0.f, 0.f);
    float2 syn = make_float2(0.f, 0.f);

    size_t idx = (size_t)i;
    const size_t stride = (size_t)n2;

    #pragma unroll 5
    for (int t = 0; t < T_STEPS; ++t, idx += stride) {
        float2 x = in[idx];

        float2 o;
        o.x = (mem.x > 1.0f) ? 1.0f : 0.0f;
        o.y = (mem.y > 1.0f) ? 1.0f : 0.0f;

        out[idx] = o;

        mem.x = (0.5f * mem.x + syn.x) * (1.0f - o.x);
        mem.y = (0.5f * mem.y + syn.y) * (1.0f - o.y);

        syn = x;
    }
}

extern "C" void kernel_launch(void* const* d_in, const int* in_sizes, int n_in,
                              void* d_out, int out_size)
{
    const float* in = (const float*)d_in[0];
    float* out = (float*)d_out;

    const int BN = in_sizes[0] / T_STEPS;  // 524288
    const int n2 = BN / 2;                 // 262144 float2 lanes

    const int threads = 256;
    const int blocks = (n2 + threads - 1) / threads;  // 1024

    lif_kernel<<<blocks, threads>>>(
        (const float2*)in, (float2*)out, n2);
}

// round 6
// speedup vs baseline: 1.0903x; 1.0903x over previous
#include <cuda_runtime.h>

// LIF neuron recurrence, fully parallel across B*N neurons, serial over T.
//   out[t]  = (mem > 1.0f) ? 1 : 0
//   mem     = (0.5f*mem + syn) * (1 - out[t])
//   syn     = in[t]
// inputs: [T=100, B=256, N=2048] fp32 contiguous; output same shape.
//
// R6: winning config (float4, 512x256, 27 warps/SM — best of 5 measured
// configs at 61.4us / 75.9% DRAM) + software-pipelined prefetch: load x(t+1)
// before storing o(t) so each warp keeps 2 reads in flight across the store
// and the LDG->syn dependency is decoupled by one full iteration.
// Evidence says ~6.0TB/s is the mixed-R/W ceiling; this is the last in-config
// MLP lever.

constexpr int T_STEPS = 100;

__global__ void __launch_bounds__(256) lif_kernel(
    const float4* __restrict__ in,
    float4* __restrict__ out,
    int n4)
{
    int i = blockIdx.x * blockDim.x + threadIdx.x;
    if (i >= n4) return;

    float4 mem = make_float4(0.f, 0.f, 0.f, 0.f);
    float4 syn = make_float4(0.f, 0.f, 0.f, 0.f);

    size_t idx = (size_t)i;
    const size_t stride = (size_t)n4;

    // Prologue: issue first load before entering the loop.
    float4 x = in[idx];

    #pragma unroll 5
    for (int t = 0; t < T_STEPS; ++t) {
        // Prefetch next input before this iteration's store.
        float4 x_next;
        if (t + 1 < T_STEPS)
            x_next = in[idx + stride];

        float4 o;
        o.x = (mem.x > 1.0f) ? 1.0f : 0.0f;
        o.y = (mem.y > 1.0f) ? 1.0f : 0.0f;
        o.z = (mem.z > 1.0f) ? 1.0f : 0.0f;
        o.w = (mem.w > 1.0f) ? 1.0f : 0.0f;

        out[idx] = o;

        mem.x = (0.5f * mem.x + syn.x) * (1.0f - o.x);
        mem.y = (0.5f * mem.y + syn.y) * (1.0f - o.y);
        mem.z = (0.5f * mem.z + syn.z) * (1.0f - o.z);
        mem.w = (0.5f * mem.w + syn.w) * (1.0f - o.w);

        syn = x;
        x = x_next;
        idx += stride;
    }
}

extern "C" void kernel_launch(void* const* d_in, const int* in_sizes, int n_in,
                              void* d_out, int out_size)
{
    const float* in = (const float*)d_in[0];
    float* out = (float*)d_out;

    const int BN = in_sizes[0] / T_STEPS;  // 524288
    const int n4 = BN / 4;                 // 131072 float4 lanes

    const int threads = 256;
    const int blocks = (n4 + threads - 1) / threads;  // 512

    lif_kernel<<<blocks, threads>>>(
        (const float4*)in, (float4*)out, n4);
}